// round 12
// baseline (speedup 1.0000x reference)
#include <cuda_runtime.h>
#include <cuda_bf16.h>
#include <math.h>
#include <stdint.h>

#define NN   4096
#define RTOT 501
#define RPAD 512
#define NLEV 5
#define CUT  16.0f              // phi exactly 0 beyond |a|>16 (exp<4e-6)

// ---- device scratch (static, BSS zero-initialized: out-of-window entries
// are NEVER written and stay exactly zero across all replays) ----
__device__ float g_Wc[NN * RPAD];   // phi/psi factors for xc (rows) : [n][r]
__device__ float g_Wr[NN * RPAD];   // factors for xr (cols)         : [m][r]
__device__ float g_T [NN * RPAD];   // T = Wc * blockdiag(D)         : [n][r]
__device__ int   g_ic[RTOT];
__device__ int   g_ir[RTOT];
__device__ float g_D [257 * 257];   // current level's D
// tf32 GEMM operands, k-PERMUTED within each 16-block: pos = (k&3)*4+(k>>2)
__device__ __align__(1024) float g_Atf[NN * RPAD];
__device__ __align__(1024) float g_Btf[NN * RPAD];

__constant__ int c_off[5] = {0, 17, 50, 115, 244};
__constant__ int c_sc [5] = {8, 16, 32, 64, 128};
__constant__ int c_K  [5] = {17, 33, 65, 129, 257};

// ---------------------------------------------------------------------------
__device__ __forceinline__ float phi_f(float a) {
    float t = 3.14159265358979323846f * a;
    if (t == 0.0f) return 1.0f;
    float a2 = a * a;
    if (a2 > CUT * CUT) return 0.0f;
    return __fdividef(sinpif(a), t) * __expf(a2 * (-1.0f / 20.48f));
}
__device__ __forceinline__ uint32_t to_tf32(float v) {
    uint32_t t;
    asm("cvt.rna.tf32.f32 %0, %1;" : "=r"(t) : "f"(v));
    return t;
}
__device__ __forceinline__ int permk(int kk) { return ((kk & 3) << 2) | (kk >> 2); }

// ---------------------------------------------------------------------------
// Windowed factor fill. grid (NN, 2): side 0 -> Wc(xc), side 1 -> Wr(xr)+Btf.
// 5 levels x 40 slots; out-of-window entries never stored (BSS zero).
// ---------------------------------------------------------------------------
__global__ void k_compute_w(const float* __restrict__ xc,
                            const float* __restrict__ xr) {
    int t = threadIdx.x;
    if (t >= 200) return;
    int n = blockIdx.x, side = blockIdx.y;
    int l = t / 40, slot = t % 40;
    int s = c_sc[l], K = c_K[l], off = c_off[l];
    float x = side ? xr[n] : xc[n];
    float fs = (float)s;
    int jlo = (int)floorf(fs * x - CUT) + s - 1;
    int jhi = (int)ceilf (fs * x + CUT) + s + 1;
    if (jlo < 0) jlo = 0;
    if (jhi > K - 1) jhi = K - 1;
    int j = jlo + slot;
    if (j > jhi) return;
    float v = phi_f(fs * x - (float)(j - s));
    int kg = off + j;
    size_t rowb = (size_t)n * RPAD;
    if (side) {
        g_Wr[rowb + kg] = v;
        g_Btf[rowb + (kg & ~15) + permk(kg & 15)] = __uint_as_float(to_tf32(v));
    } else {
        g_Wc[rowb + kg] = v;
    }
}

__device__ __forceinline__ int nearest_sorted(const float* __restrict__ x, float tgt) {
    int lo = 0, hi = NN;
    while (lo < hi) { int mid = (lo + hi) >> 1; if (x[mid] < tgt) lo = mid + 1; else hi = mid; }
    if (lo == 0)  return 0;
    if (lo == NN) return NN - 1;
    float d1 = fabsf(x[lo - 1] - tgt);
    float d2 = fabsf(x[lo] - tgt);
    return (d1 <= d2) ? (lo - 1) : lo;
}

__global__ void k_compute_idx(const float* __restrict__ xc,
                              const float* __restrict__ xr) {
    int col = blockIdx.x * blockDim.x + threadIdx.x;
    if (col >= RTOT) return;
    int l = (col < 17) ? 0 : (col < 50) ? 1 : (col < 115) ? 2 : (col < 244) ? 3 : 4;
    int m = (col - c_off[l]) - c_sc[l];
    float tgt = (float)m / (float)c_sc[l];
    g_ic[col] = nearest_sorted(xc, tgt);
    g_ir[col] = nearest_sorted(xr, tgt);
}

// ---------------------------------------------------------------------------
// D[a,b] = thresh( img[ic_a, ir_b] - U ), U windowed per previous level.
// ---------------------------------------------------------------------------
__global__ void k_compute_D(const float* __restrict__ img,
                            const float* __restrict__ xr,
                            int off, int K, int thresh_on) {
    __shared__ float Trow[256];
    int a   = blockIdx.y;
    int b   = blockIdx.x * blockDim.x + threadIdx.x;
    int ica = g_ic[off + a];
    for (int r = threadIdx.x; r < off; r += blockDim.x)
        Trow[r] = g_T[(size_t)ica * RPAD + r];
    __syncthreads();
    if (b >= K) return;
    int irb = g_ir[off + b];
    const float* wr = &g_Wr[(size_t)irb * RPAD];
    float u = 0.0f;
    if (off > 0) {
        float x = xr[irb];
#pragma unroll
        for (int l = 0; l < 4; ++l) {
            if (c_off[l] >= off) break;
            int s = c_sc[l];
            float fs = (float)s;
            int jlo = (int)floorf(fs * x - CUT) + s - 1;
            int jhi = (int)ceilf (fs * x + CUT) + s + 1;
            if (jlo < 0) jlo = 0;
            if (jhi > c_K[l] - 1) jhi = c_K[l] - 1;
            int base = c_off[l];
            for (int j = jlo; j <= jhi; ++j)
                u += Trow[base + j] * wr[base + j];
        }
    }
    float d = img[(size_t)ica * NN + irb] - u;
    if (thresh_on && fabsf(d) <= 0.01f) d = 0.0f;
    g_D[a * K + b] = d;
}

// Windowed over a; emits tf32 A operand in the permuted layout.
__global__ void k_compute_T(int off, int K, int s, const float* __restrict__ xc) {
    int b = blockIdx.x * blockDim.x + threadIdx.x;
    int n = blockIdx.y * blockDim.y + threadIdx.y;
    if (b >= K) return;
    float fs = (float)s, x = xc[n];
    int alo = (int)floorf(fs * x - CUT) + s - 1;
    int ahi = (int)ceilf (fs * x + CUT) + s + 1;
    if (alo < 0) alo = 0;
    if (ahi > K - 1) ahi = K - 1;
    const float* wc = &g_Wc[(size_t)n * RPAD + off];
    float acc = 0.0f;
    for (int a = alo; a <= ahi; ++a)
        acc += wc[a] * g_D[a * K + b];
    size_t rowb = (size_t)n * RPAD;
    int kg = off + b;
    g_T[rowb + kg] = acc;
    g_Atf[rowb + (kg & ~15) + permk(kg & 15)] = __uint_as_float(to_tf32(acc));
}

// ---------------------------------------------------------------------------
// tf32 GEMM, per-tile k-window, 3-stage cp.async pipeline, permuted operand
// layout -> LDS.128 fragment loads (both k8 steps per load). CTA 128x128,
// chunk K=16, 8 warps, warp tile 64x32, m16n8k8.
// ---------------------------------------------------------------------------
#define TSTAGE 16384
#define NSTG   3
#define TGSMEM (NSTG * TSTAGE + 256)

__device__ __forceinline__ uint32_t smem_u32(const void* p) {
    uint32_t a;
    asm("{ .reg .u64 t; cvta.to.shared.u64 t, %1; cvt.u32.u64 %0, t; }"
        : "=r"(a) : "l"(p));
    return a;
}
__device__ __forceinline__ void cp16(uint32_t s, const void* g) {
    asm volatile("cp.async.cg.shared.global [%0], [%1], 16;" :: "r"(s), "l"(g));
}
__device__ __forceinline__ void mma_tf32(float& d0, float& d1, float& d2, float& d3,
                                         float a0, float a1, float a2, float a3,
                                         float b0, float b1) {
    asm volatile(
        "mma.sync.aligned.m16n8k8.row.col.f32.tf32.tf32.f32 "
        "{%0,%1,%2,%3}, {%4,%5,%6,%7}, {%8,%9}, {%0,%1,%2,%3};"
        : "+f"(d0), "+f"(d1), "+f"(d2), "+f"(d3)
        : "r"(__float_as_uint(a0)), "r"(__float_as_uint(a1)),
          "r"(__float_as_uint(a2)), "r"(__float_as_uint(a3)),
          "r"(__float_as_uint(b0)), "r"(__float_as_uint(b1)));
}

__global__ __launch_bounds__(256, 2) void k_gemm_tf32(float* __restrict__ C,
                                                      const float* __restrict__ xr) {
    extern __shared__ char smem[];
    const uint32_t sb = smem_u32(smem);
    int* s_list = (int*)(smem + NSTG * TSTAGE);
    const int tid  = threadIdx.x;
    const int wid  = tid >> 5, lane = tid & 31;
    const int n0   = blockIdx.y * 128;   // C rows  (A = T rows)
    const int m0   = blockIdx.x * 128;   // C cols  (B = Wr rows)
    const int wm   = (wid >> 2) * 64;
    const int wn   = (wid & 3) * 32;

    // ---- active k-block list from the B tile's xr range (exact) ----
    if (tid == 0) {
        float xmin = xr[m0], xmax = xr[m0 + 127];
        uint32_t mask = 0;
#pragma unroll
        for (int l = 0; l < 5; ++l) {
            int s = c_sc[l];
            float fs = (float)s;
            int lo = c_off[l] + s + (int)floorf(fs * xmin - CUT) - 1;
            int hi = c_off[l] + s + (int)ceilf (fs * xmax + CUT) + 1;
            if (lo < c_off[l]) lo = c_off[l];
            if (hi > c_off[l] + c_K[l] - 1) hi = c_off[l] + c_K[l] - 1;
            if (lo > hi) continue;
            for (int b = (lo >> 4); b <= (hi >> 4); ++b) mask |= (1u << b);
        }
        int nb = 0;
        while (mask) { int b = __ffs(mask) - 1; mask &= mask - 1; s_list[1 + nb++] = b; }
        s_list[0] = nb;
    }
    __syncthreads();
    const int nb = s_list[0];       // >= 4 always (levels 0-1 fully active)

    float acc[4][4][4];
#pragma unroll
    for (int i = 0; i < 4; ++i)
#pragma unroll
        for (int j = 0; j < 4; ++j)
#pragma unroll
            for (int q = 0; q < 4; ++q) acc[i][j][q] = 0.0f;

    const float* Ab = g_Atf + (size_t)n0 * RPAD;
    const float* Bb = g_Btf + (size_t)m0 * RPAD;

    auto load_chunk = [&](int blk, int stage) {
        const int k0 = blk * 16;
        const uint32_t stb = sb + stage * TSTAGE;
#pragma unroll
        for (int i = 0; i < 4; ++i) {           // 1024 16B units / 256 thr
            int u   = tid + i * 256;
            int arr = u >> 9, rem = u & 511;
            int row = rem >> 2, cq = rem & 3;
            const float* gp = (arr ? Bb : Ab) + (size_t)row * RPAD + k0 + cq * 4;
            cp16(stb + arr * 8192 + row * 64 + cq * 16, gp);
        }
        asm volatile("cp.async.commit_group;" ::: "memory");
    };

    const int pre = nb < NSTG ? nb : NSTG;
    for (int p = 0; p < pre; ++p) load_chunk(s_list[1 + p], p);

    const int aq = lane >> 2;         // 0..7  (row-in-8 / col-in-8)
    const int ak = lane & 3;          // 0..3  (k lane)

    for (int c = 0; c < nb; ++c) {
        const int stage = c % NSTG;
        const int rem = nb - 1 - c;
        if (rem >= 2)      asm volatile("cp.async.wait_group 2;" ::: "memory");
        else if (rem == 1) asm volatile("cp.async.wait_group 1;" ::: "memory");
        else               asm volatile("cp.async.wait_group 0;" ::: "memory");
        __syncthreads();

        const char* sA = smem + stage * TSTAGE;
        const char* sB = sA + 8192;

        // B fragments for both k8 steps: one LDS.128 per nj
        float4 bf[4];
#pragma unroll
        for (int nj = 0; nj < 4; ++nj)
            bf[nj] = *(const float4*)(sB + (wn + nj * 8 + aq) * 64 + ak * 16);

#pragma unroll
        for (int mi = 0; mi < 4; ++mi) {
            int r = wm + mi * 16 + aq;
            float4 a0 = *(const float4*)(sA + r * 64 + ak * 16);        // rows r
            float4 a1 = *(const float4*)(sA + (r + 8) * 64 + ak * 16);  // rows r+8
#pragma unroll
            for (int nj = 0; nj < 4; ++nj) {
                mma_tf32(acc[mi][nj][0], acc[mi][nj][1],
                         acc[mi][nj][2], acc[mi][nj][3],
                         a0.x, a1.x, a0.y, a1.y, bf[nj].x, bf[nj].y);   // k8 #0
                mma_tf32(acc[mi][nj][0], acc[mi][nj][1],
                         acc[mi][nj][2], acc[mi][nj][3],
                         a0.z, a1.z, a0.w, a1.w, bf[nj].z, bf[nj].w);   // k8 #1
            }
        }

        __syncthreads();
        if (c + NSTG < nb) load_chunk(s_list[1 + c + NSTG], stage);
    }

    // Epilogue
#pragma unroll
    for (int mi = 0; mi < 4; ++mi) {
        int row = n0 + wm + mi * 16 + (lane >> 2);
#pragma unroll
        for (int nj = 0; nj < 4; ++nj) {
            int col = m0 + wn + nj * 8 + (lane & 3) * 2;
            float2* p0 = (float2*)(C + (size_t)row * NN + col);
            float2* p1 = (float2*)(C + (size_t)(row + 8) * NN + col);
            *p0 = make_float2(acc[mi][nj][0], acc[mi][nj][1]);
            *p1 = make_float2(acc[mi][nj][2], acc[mi][nj][3]);
        }
    }
}

// ---------------------------------------------------------------------------
extern "C" void kernel_launch(void* const* d_in, const int* in_sizes, int n_in,
                              void* d_out, int out_size) {
    const float* img = (const float*)d_in[0];
    const float* xc  = (const float*)d_in[1];
    const float* xr  = (const float*)d_in[2];
    float* out = (float*)d_out;

    (void)in_sizes; (void)n_in; (void)out_size;

    cudaFuncSetAttribute(k_gemm_tf32, cudaFuncAttributeMaxDynamicSharedMemorySize,
                         TGSMEM);

    // 1. nearest indices (tiny) + windowed factors (+ fused tf32 of B)
    k_compute_idx<<<2, 256>>>(xc, xr);
    k_compute_w<<<dim3(NN, 2), 256>>>(xc, xr);

    // 2. per-level D and T blocks (sequential: U depends on previous T)
    static const int offs[NLEV] = {0, 17, 50, 115, 244};
    static const int Ks[NLEV]   = {17, 33, 65, 129, 257};
    static const int Ss[NLEV]   = {8, 16, 32, 64, 128};
    for (int l = 0; l < NLEV; ++l) {
        dim3 gD((Ks[l] + 255) / 256, Ks[l]);
        k_compute_D<<<gD, 256>>>(img, xr, offs[l], Ks[l], l > 0 ? 1 : 0);
        dim3 bT(64, 4), gT((Ks[l] + 63) / 64, NN / 4);
        k_compute_T<<<gT, bT>>>(offs[l], Ks[l], Ss[l], xc);
    }

    // 3. out = T * Wr^T, tf32 tensor cores + per-tile k-window
    dim3 gg(NN / 128, NN / 128);   // (32, 32)
    k_gemm_tf32<<<gg, 256, TGSMEM>>>(out, xr);
}

// round 13
// speedup vs baseline: 1.5472x; 1.5472x over previous
#include <cuda_runtime.h>
#include <cuda_bf16.h>
#include <math.h>
#include <stdint.h>

#define NN   4096
#define RTOT 501
#define RPAD 512
#define NLEV 5
#define CUT  16.0f              // phi exactly 0 beyond |a|>16 (exp<4e-6)

// ---- device scratch (static allocation: allowed) ----
__device__ float g_Wc[NN * RPAD];   // phi/psi factors for xc (rows) : [n][r]
__device__ float g_Wr[NN * RPAD];   // factors for xr (cols)         : [m][r]
__device__ float g_T [NN * RPAD];   // T = Wc * blockdiag(D)         : [n][r]
__device__ int   g_ic[RTOT];
__device__ int   g_ir[RTOT];
__device__ float g_D [257 * 257];   // current level's D
// tf32-rounded GEMM operands (bit patterns stored as float)
__device__ __align__(1024) float g_Atf[NN * RPAD];
__device__ __align__(1024) float g_Btf[NN * RPAD];

// ---------------------------------------------------------------------------
// phi(a) = sin(pi a) * exp(-a^2/20.48) / (pi a), phi(0)=1.
// EXACT zero for |a| > CUT — all windows below rely on it.
// ---------------------------------------------------------------------------
__device__ __forceinline__ float phi_f(float a) {
    float t = 3.14159265358979323846f * a;
    if (t == 0.0f) return 1.0f;
    float a2 = a * a;
    if (a2 > CUT * CUT) return 0.0f;
    return __fdividef(sinpif(a), t) * __expf(a2 * (-1.0f / 20.48f));
}

__device__ __forceinline__ void col_to_level(int col, int& off, int& s) {
    if (col < 17)       { off = 0;   s = 8;   }
    else if (col < 50)  { off = 17;  s = 16;  }
    else if (col < 115) { off = 50;  s = 32;  }
    else if (col < 244) { off = 115; s = 64;  }
    else                { off = 244; s = 128; }
}

__device__ __forceinline__ uint32_t to_tf32(float v) {
    uint32_t t;
    asm("cvt.rna.tf32.f32 %0, %1;" : "=r"(t) : "f"(v));
    return t;
}

// Fills Wc, Wr; writes tf32 B operand; zeroes pads of everything.
__global__ void k_compute_w(const float* __restrict__ xc,
                            const float* __restrict__ xr) {
    int idx = blockIdx.x * blockDim.x + threadIdx.x;
    if (idx >= NN * RPAD) return;
    int n   = idx >> 9;
    int col = idx & (RPAD - 1);
    if (col >= RTOT) {
        g_Wc[idx] = 0.0f; g_Wr[idx] = 0.0f; g_T[idx] = 0.0f;
        g_Atf[idx] = 0.0f; g_Btf[idx] = 0.0f;
        return;
    }
    int off, s;
    col_to_level(col, off, s);
    int m = (col - off) - s;
    float fs = (float)s, fm = (float)m;
    float wr = phi_f(fs * xr[n] - fm);
    g_Wc[idx] = phi_f(fs * xc[n] - fm);
    g_Wr[idx] = wr;
    g_Btf[idx] = __uint_as_float(to_tf32(wr));
}

__device__ __forceinline__ int nearest_sorted(const float* __restrict__ x, float tgt) {
    int lo = 0, hi = NN;
    while (lo < hi) { int mid = (lo + hi) >> 1; if (x[mid] < tgt) lo = mid + 1; else hi = mid; }
    if (lo == 0)  return 0;
    if (lo == NN) return NN - 1;
    float d1 = fabsf(x[lo - 1] - tgt);
    float d2 = fabsf(x[lo] - tgt);
    return (d1 <= d2) ? (lo - 1) : lo;
}

__global__ void k_compute_idx(const float* __restrict__ xc,
                              const float* __restrict__ xr) {
    int col = blockIdx.x * blockDim.x + threadIdx.x;
    if (col >= RTOT) return;
    int off, s;
    col_to_level(col, off, s);
    int m = (col - off) - s;
    float tgt = (float)m / (float)s;
    g_ic[col] = nearest_sorted(xc, tgt);
    g_ir[col] = nearest_sorted(xr, tgt);
}

// ---------------------------------------------------------------------------
// D[a,b] = thresh( img[ic_a, ir_b] - U ), U = sum_r T[ic_a,r]*Wr[ir_b,r].
// The r-dot is windowed per previous level: Wr[ir_b, off_l + j] is exactly
// zero outside |s_l * x - (j - s_l)| <= CUT.
// ---------------------------------------------------------------------------
__global__ void k_compute_D(const float* __restrict__ img,
                            const float* __restrict__ xr,
                            int off, int K, int thresh_on) {
    __shared__ float Trow[256];
    int a   = blockIdx.y;
    int b   = blockIdx.x * blockDim.x + threadIdx.x;
    int ica = g_ic[off + a];
    for (int r = threadIdx.x; r < off; r += blockDim.x)
        Trow[r] = g_T[(size_t)ica * RPAD + r];
    __syncthreads();
    if (b >= K) return;
    int irb = g_ir[off + b];
    const float* wr = &g_Wr[(size_t)irb * RPAD];
    float u = 0.0f;
    if (off > 0) {
        float x = xr[irb];
        const int loff[4] = {0, 17, 50, 115};
        const int lsc[4]  = {8, 16, 32, 64};
        const int lK[4]   = {17, 33, 65, 129};
#pragma unroll
        for (int l = 0; l < 4; ++l) {
            if (loff[l] >= off) break;
            float fs = (float)lsc[l];
            int jlo = (int)floorf(fs * x - CUT) + lsc[l] - 1;
            int jhi = (int)ceilf (fs * x + CUT) + lsc[l] + 1;
            if (jlo < 0) jlo = 0;
            if (jhi > lK[l] - 1) jhi = lK[l] - 1;
            int base = loff[l];
            for (int j = jlo; j <= jhi; ++j)
                u += Trow[base + j] * wr[base + j];
        }
    }
    float d = img[(size_t)ica * NN + irb] - u;
    if (thresh_on && fabsf(d) <= 0.01f) d = 0.0f;
    g_D[a * K + b] = d;
}

// Windowed over a; also emits the tf32 A operand (fused cvt).
__global__ void k_compute_T(int off, int K, int s, const float* __restrict__ xc) {
    int b = blockIdx.x * blockDim.x + threadIdx.x;
    int n = blockIdx.y * blockDim.y + threadIdx.y;
    if (b >= K) return;
    float fs = (float)s, x = xc[n];
    int alo = (int)floorf(fs * x - CUT) + s - 1;
    int ahi = (int)ceilf (fs * x + CUT) + s + 1;
    if (alo < 0) alo = 0;
    if (ahi > K - 1) ahi = K - 1;
    const float* wc = &g_Wc[(size_t)n * RPAD + off];
    float acc = 0.0f;
    for (int a = alo; a <= ahi; ++a)
        acc += wc[a] * g_D[a * K + b];
    size_t idx = (size_t)n * RPAD + off + b;
    g_T[idx] = acc;
    g_Atf[idx] = __uint_as_float(to_tf32(acc));
}

// ---------------------------------------------------------------------------
// tf32 GEMM with per-tile k-window: C = T * Wr^T over only the 16-col k-blocks
// where the B tile (sorted xr) can be nonzero. CTA tile 128x128, chunk K=16,
// 2-stage cp.async (2 x 16KB), 8 warps, warp tile 64x32, m16n8k8 MMAs.
// ---------------------------------------------------------------------------
#define TSTAGE 16384
#define TGSMEM (2 * TSTAGE + 256)

__device__ __forceinline__ uint32_t soff(uint32_t r, uint32_t k) {
    return r * 64 + ((((k >> 2) ^ ((r >> 1) & 3)) & 3) << 4) + ((k & 3) << 2);
}
__device__ __forceinline__ uint32_t smem_u32(const void* p) {
    uint32_t a;
    asm("{ .reg .u64 t; cvta.to.shared.u64 t, %1; cvt.u32.u64 %0, t; }"
        : "=r"(a) : "l"(p));
    return a;
}
__device__ __forceinline__ void cp16(uint32_t s, const void* g) {
    asm volatile("cp.async.cg.shared.global [%0], [%1], 16;" :: "r"(s), "l"(g));
}
__device__ __forceinline__ void mma_tf32(float& d0, float& d1, float& d2, float& d3,
                                         uint32_t a0, uint32_t a1, uint32_t a2,
                                         uint32_t a3, uint32_t b0, uint32_t b1) {
    asm volatile(
        "mma.sync.aligned.m16n8k8.row.col.f32.tf32.tf32.f32 "
        "{%0,%1,%2,%3}, {%4,%5,%6,%7}, {%8,%9}, {%0,%1,%2,%3};"
        : "+f"(d0), "+f"(d1), "+f"(d2), "+f"(d3)
        : "r"(a0), "r"(a1), "r"(a2), "r"(a3), "r"(b0), "r"(b1));
}

__global__ __launch_bounds__(256, 2) void k_gemm_tf32(float* __restrict__ C,
                                                      const float* __restrict__ xr) {
    extern __shared__ char smem[];
    const uint32_t sb = smem_u32(smem);
    int* s_list = (int*)(smem + 2 * TSTAGE);
    const int tid  = threadIdx.x;
    const int wid  = tid >> 5, lane = tid & 31;
    const int n0   = blockIdx.y * 128;   // C rows  (A = T rows)
    const int m0   = blockIdx.x * 128;   // C cols  (B = Wr rows)
    const int wm   = (wid >> 2) * 64;
    const int wn   = (wid & 3) * 32;

    // ---- active k-block list from the B tile's xr range (exact) ----
    if (tid == 0) {
        float xmin = xr[m0], xmax = xr[m0 + 127];
        const int off[5] = {0, 17, 50, 115, 244};
        const int sl[5]  = {8, 16, 32, 64, 128};
        const int kl[5]  = {17, 33, 65, 129, 257};
        uint32_t mask = 0;
#pragma unroll
        for (int l = 0; l < 5; ++l) {
            float fs = (float)sl[l];
            int lo = off[l] + sl[l] + (int)floorf(fs * xmin - CUT) - 1;
            int hi = off[l] + sl[l] + (int)ceilf (fs * xmax + CUT) + 1;
            if (lo < off[l]) lo = off[l];
            if (hi > off[l] + kl[l] - 1) hi = off[l] + kl[l] - 1;
            if (lo > hi) continue;
            for (int b = (lo >> 4); b <= (hi >> 4); ++b) mask |= (1u << b);
        }
        int nb = 0;
        while (mask) { int b = __ffs(mask) - 1; mask &= mask - 1; s_list[1 + nb++] = b; }
        s_list[0] = nb;
    }
    __syncthreads();
    const int nb = s_list[0];       // >= 4 always (levels 0-1 fully active)

    float acc[4][4][4];
#pragma unroll
    for (int i = 0; i < 4; ++i)
#pragma unroll
        for (int j = 0; j < 4; ++j)
#pragma unroll
            for (int q = 0; q < 4; ++q) acc[i][j][q] = 0.0f;

    const float* Ab = g_Atf + (size_t)n0 * RPAD;
    const float* Bb = g_Btf + (size_t)m0 * RPAD;

    auto load_chunk = [&](int blk, int stage) {
        const int k0 = blk * 16;
        const uint32_t stb = sb + stage * TSTAGE;
#pragma unroll
        for (int i = 0; i < 4; ++i) {           // 1024 16B units / 256 thr
            int u   = tid + i * 256;
            int arr = u >> 9, rem = u & 511;
            int row = rem >> 2, cq = rem & 3;
            const float* gp = (arr ? Bb : Ab) + (size_t)row * RPAD + k0 + cq * 4;
            cp16(stb + arr * 8192 + row * 64 + (((cq ^ ((row >> 1) & 3)) & 3) << 4), gp);
        }
        asm volatile("cp.async.commit_group;" ::: "memory");
    };

    load_chunk(s_list[1], 0);
    load_chunk(s_list[2], 1);   // safe: nb >= 2

    const int aq = lane >> 2;         // 0..7
    const int ak = lane & 3;          // 0..3

    for (int c = 0; c < nb; ++c) {
        const int stage = c & 1;
        if (c < nb - 1) asm volatile("cp.async.wait_group 1;" ::: "memory");
        else            asm volatile("cp.async.wait_group 0;" ::: "memory");
        __syncthreads();

        const char* sA = smem + stage * TSTAGE;
        const char* sB = sA + 8192;

#pragma unroll
        for (int ks = 0; ks < 2; ++ks) {        // two k8 steps in chunk16
            const int kb = ks * 8;
            uint32_t a[4][4];
#pragma unroll
            for (int mi = 0; mi < 4; ++mi) {
                int r = wm + mi * 16 + aq;
                a[mi][0] = *(const uint32_t*)(sA + soff(r,     kb + ak));
                a[mi][1] = *(const uint32_t*)(sA + soff(r + 8, kb + ak));
                a[mi][2] = *(const uint32_t*)(sA + soff(r,     kb + ak + 4));
                a[mi][3] = *(const uint32_t*)(sA + soff(r + 8, kb + ak + 4));
            }
            uint32_t b[4][2];
#pragma unroll
            for (int nj = 0; nj < 4; ++nj) {
                int r = wn + nj * 8 + aq;
                b[nj][0] = *(const uint32_t*)(sB + soff(r, kb + ak));
                b[nj][1] = *(const uint32_t*)(sB + soff(r, kb + ak + 4));
            }
#pragma unroll
            for (int mi = 0; mi < 4; ++mi)
#pragma unroll
                for (int nj = 0; nj < 4; ++nj)
                    mma_tf32(acc[mi][nj][0], acc[mi][nj][1],
                             acc[mi][nj][2], acc[mi][nj][3],
                             a[mi][0], a[mi][1], a[mi][2], a[mi][3],
                             b[nj][0], b[nj][1]);
        }

        __syncthreads();
        if (c + 2 < nb) load_chunk(s_list[1 + c + 2], stage);
    }

    // Epilogue
#pragma unroll
    for (int mi = 0; mi < 4; ++mi) {
        int row = n0 + wm + mi * 16 + (lane >> 2);
#pragma unroll
        for (int nj = 0; nj < 4; ++nj) {
            int col = m0 + wn + nj * 8 + (lane & 3) * 2;
            float2* p0 = (float2*)(C + (size_t)row * NN + col);
            float2* p1 = (float2*)(C + (size_t)(row + 8) * NN + col);
            *p0 = make_float2(acc[mi][nj][0], acc[mi][nj][1]);
            *p1 = make_float2(acc[mi][nj][2], acc[mi][nj][3]);
        }
    }
}

// ---------------------------------------------------------------------------
extern "C" void kernel_launch(void* const* d_in, const int* in_sizes, int n_in,
                              void* d_out, int out_size) {
    const float* img = (const float*)d_in[0];
    const float* xc  = (const float*)d_in[1];
    const float* xr  = (const float*)d_in[2];
    float* out = (float*)d_out;

    (void)in_sizes; (void)n_in; (void)out_size;

    cudaFuncSetAttribute(k_gemm_tf32, cudaFuncAttributeMaxDynamicSharedMemorySize,
                         TGSMEM);

    // 1. factors (+ fused tf32 cvt of B)
    k_compute_w<<<(NN * RPAD) / 256, 256>>>(xc, xr);
    // 2. nearest indices
    k_compute_idx<<<2, 256>>>(xc, xr);

    // 3. per-level D and T blocks (sequential: U depends on previous T)
    static const int offs[NLEV] = {0, 17, 50, 115, 244};
    static const int Ks[NLEV]   = {17, 33, 65, 129, 257};
    static const int Ss[NLEV]   = {8, 16, 32, 64, 128};
    for (int l = 0; l < NLEV; ++l) {
        dim3 gD((Ks[l] + 255) / 256, Ks[l]);
        k_compute_D<<<gD, 256>>>(img, xr, offs[l], Ks[l], l > 0 ? 1 : 0);
        dim3 bT(64, 4), gT((Ks[l] + 63) / 64, NN / 4);
        k_compute_T<<<gT, bT>>>(offs[l], Ks[l], Ss[l], xc);
    }

    // 4. out = T * Wr^T, tf32 tensor cores + per-tile k-window
    dim3 gg(NN / 128, NN / 128);   // (32, 32)
    k_gemm_tf32<<<gg, 256, TGSMEM>>>(out, xr);
}